// round 15
// baseline (speedup 1.0000x reference)
#include <cuda_runtime.h>
#include <cuda_fp16.h>
#include <cstdint>

// ---------------------------------------------------------------------------
// out[n, e*4+a] = sum_{m,b} adj[n, m*4+b] * Vk[m*4+b, e*4+a]
// C[4096,128] = A[4096,16384] @ Vk.  A fp32 -> fp16 in-kernel, B packed fp16.
// mma.m16n8k16.f16.f32.  Split-K = 9.  512-thr CTAs (16 warps, 32x32 warp
// tile) for 32 warps/SM occupancy — tensor pipe was only 42% busy at 16.
// ---------------------------------------------------------------------------
#define NODES 4096
#define KTOT  16384
#define NC    128

#define BM 128
#define BK 32
#define SPLITS 9
#define KB_TOTAL (KTOT / BK)    // 512 k-blocks
#define KB_PER   57             // splits 0..7: 57, split 8: 56

// B operand, fp16, fragment-packed per 16-k slab:
//   value B[k][col] at g_Vp[slab*2048 + col*16 + c*4 + j]
//   slab=k>>4, kk=k&15, c=(kk>>1)&3, j=(kk&1)|((kk>>3)<<1)
__device__ __align__(128) __half g_Vp[KTOT * NC];     // 4 MB
__device__ float g_part[SPLITS * NODES * NC];         // 18 MB

// ------------------------------ helpers ------------------------------------
__device__ __forceinline__ uint32_t smem_u32(const void* p) {
    uint32_t a;
    asm("{ .reg .u64 t; cvta.to.shared.u64 t, %1; cvt.u32.u64 %0, t; }"
        : "=r"(a) : "l"(p));
    return a;
}
__device__ __forceinline__ void cp_async16(uint32_t dst, const void* src) {
    asm volatile("cp.async.cg.shared.global [%0], [%1], 16;"
                 :: "r"(dst), "l"(src) : "memory");
}
__device__ __forceinline__ void cp_commit() {
    asm volatile("cp.async.commit_group;" ::: "memory");
}
template <int N>
__device__ __forceinline__ void cp_wait() {
    asm volatile("cp.async.wait_group %0;" :: "n"(N) : "memory");
}
__device__ __forceinline__ void ldmatrix_x4(uint32_t* r, uint32_t addr) {
    asm volatile("ldmatrix.sync.aligned.m8n8.x4.shared.b16 {%0,%1,%2,%3}, [%4];"
                 : "=r"(r[0]), "=r"(r[1]), "=r"(r[2]), "=r"(r[3]) : "r"(addr));
}
__device__ __forceinline__ void mma_f16(float* d, const uint32_t* a,
                                        const uint32_t* b) {
    asm volatile(
        "mma.sync.aligned.m16n8k16.row.col.f32.f16.f16.f32 "
        "{%0,%1,%2,%3}, {%4,%5,%6,%7}, {%8,%9}, {%0,%1,%2,%3};"
        : "+f"(d[0]), "+f"(d[1]), "+f"(d[2]), "+f"(d[3])
        : "r"(a[0]), "r"(a[1]), "r"(a[2]), "r"(a[3]), "r"(b[0]), "r"(b[1]));
}
__device__ __forceinline__ uint32_t cvt_f16x2(float lo, float hi) {
    uint32_t h;
    asm("cvt.rn.f16x2.f32 %0, %1, %2;" : "=r"(h) : "f"(hi), "f"(lo));
    return h;
}

// ---------------------------------------------------------------------------
// prep: 512 blocks x 256 thr; thread = (slab nh 0..1, column col 0..127).
// Rotation identity keeps ALL hot-loop indices compile-time.  (validated R13)
// ---------------------------------------------------------------------------
__global__ __launch_bounds__(256) void prep_kernel(const float* __restrict__ x,
                                                   const float* __restrict__ w) {
    __shared__ float ws[4096];                          // full W, 16 KB
    __shared__ float xs[1024];                          // 8 nodes x 128, 4 KB

    const int t = threadIdx.x;
#pragma unroll
    for (int i = 0; i < 4; i++)
        ((float4*)ws)[t + i * 256] = ((const float4*)w)[t + i * 256];
    ((float4*)xs)[t] =
        ((const float4*)(x + (size_t)blockIdx.x * 1024))[t];
    __syncthreads();

    const int nh = t >> 7;                              // slab in block
    const int col = t & 127;
    const int a = col & 3, e = col >> 2;

    int woff[4];
#pragma unroll
    for (int j = 0; j < 4; j++) woff[j] = e * 4 + ((a - j) & 3);

    float acc[4][4];                                    // [mi][j] rotated
#pragma unroll
    for (int mi = 0; mi < 4; mi++)
#pragma unroll
        for (int j = 0; j < 4; j++) acc[mi][j] = 0.f;

#pragma unroll
    for (int d = 0; d < 32; d++) {
        float wr[4];
#pragma unroll
        for (int j = 0; j < 4; j++) wr[j] = ws[d * 128 + woff[j]];
#pragma unroll
        for (int mi = 0; mi < 4; mi++) {
            const float4 xv = *(const float4*)&xs[(nh * 4 + mi) * 128 + d * 4];
            acc[mi][0] += xv.x * wr[0];
            acc[mi][1] += xv.y * wr[1];
            acc[mi][2] += xv.z * wr[2];
            acc[mi][3] += xv.w * wr[3];
        }
    }

    __align__(16) __half hbuf[16];
#pragma unroll
    for (int mi = 0; mi < 4; mi++)
#pragma unroll
        for (int j = 0; j < 4; j++) {
            const int b = (a - j) & 3;
            const int kk = mi * 4 + b;
            const int pos = ((kk >> 1) & 3) * 4 + (kk & 1) + ((kk >> 3) << 1);
            hbuf[pos] = __float2half_rn(acc[mi][j]);
        }
    const size_t slab = (size_t)blockIdx.x * 2 + nh;
    uint4* dst = (uint4*)(g_Vp + slab * 2048 + col * 16);
    dst[0] = ((const uint4*)hbuf)[0];
    dst[1] = ((const uint4*)hbuf)[1];
}

// ---------------------------------------------------------------------------
// GEMM: grid (32 m-tiles, 9 splits), 512 thr = 16 warps (4m x 4n),
// warp tile 32x32, mma m16n8k16 f16.f32.  2 CTAs/SM -> 32 warps/SM.
// ---------------------------------------------------------------------------
__global__ __launch_bounds__(512, 2) void gemm_kernel(const float* __restrict__ A) {
    __shared__ __align__(16) __half Asm[2][128 * 32];   // 16 KB, swizzled
    __shared__ __align__(16) __half Bsm[3][32 * 128];   // 24 KB, packed

    const uint32_t asb = smem_u32(Asm);
    const uint32_t bsb = smem_u32(Bsm);
    const int tid = threadIdx.x;
    const int lane = tid & 31;
    const int wid = tid >> 5;                           // 0..15
    const int wm = (wid & 3) * 32;
    const int wn = (wid >> 2) * 32;
    const int g = lane >> 2;
    const int c = lane & 3;

    const int m0 = blockIdx.x * BM;
    const int kb0 = blockIdx.y * KB_PER;
    const int cnt = min(KB_PER, KB_TOTAL - kb0);
    const int k0 = kb0 * BK;
    const __half* Bsrc = g_Vp + (size_t)(k0 >> 4) * 2048;

    const int row_l = (lane & 7) | (((lane >> 3) & 1) << 3);
    const int khalf = lane >> 4;
    uint32_t a_addr[2][2];
#pragma unroll
    for (int mi = 0; mi < 2; mi++)
#pragma unroll
        for (int ks = 0; ks < 2; ks++) {
            const int r = wm + mi * 16 + row_l;
            const int ch = (ks * 2 + khalf) ^ (r & 3);
            a_addr[mi][ks] = asb + (uint32_t)(r * 64 + ch * 16);
        }
    const uint32_t b_off = (uint32_t)((wn + g) * 32 + c * 8);

    const int a_row = tid >> 3;                         // 0..63
    const int a_kq = tid & 7;

    float acc[2][4][4];
#pragma unroll
    for (int mi = 0; mi < 2; mi++)
#pragma unroll
        for (int ni = 0; ni < 4; ni++)
#pragma unroll
            for (int j = 0; j < 4; j++) acc[mi][ni][j] = 0.f;

    float4 pf[2];
    auto ldgA = [&](int it) {
        if (it < cnt) {
            const int ko = k0 + it * BK;
#pragma unroll
            for (int p = 0; p < 2; p++)
                pf[p] = *(const float4*)(A + (size_t)(m0 + a_row + p * 64) * KTOT +
                                         ko + a_kq * 4);
        }
    };
    auto stsA = [&](int it) {
        if (it < cnt) {
            const uint32_t base = asb + (uint32_t)(it & 1) * 8192u;
#pragma unroll
            for (int p = 0; p < 2; p++) {
                const int row = a_row + p * 64;
                const uint32_t off =
                    (uint32_t)(row * 64 + (((a_kq >> 1) ^ (row & 3)) * 16) +
                               (a_kq & 1) * 8);
                const uint32_t h0 = cvt_f16x2(pf[p].x, pf[p].y);
                const uint32_t h1 = cvt_f16x2(pf[p].z, pf[p].w);
                asm volatile("st.shared.v2.b32 [%0], {%1, %2};"
                             :: "r"(base + off), "r"(h0), "r"(h1) : "memory");
            }
        }
    };
    auto cpB = [&](int it) {
        if (it < cnt) {
            const uint32_t bd = bsb + (uint32_t)(it % 3) * 8192u;
            const char* src = (const char*)(Bsrc + (size_t)it * 4096);
            cp_async16(bd + (uint32_t)tid * 16, src + tid * 16);
        }
    };

    // prologue
    ldgA(0);
    cpB(0); cp_commit();
    cpB(1); cp_commit();
    stsA(0);
    ldgA(1);

    for (int it = 0; it < cnt; it++) {
        cp_wait<1>();
        __syncthreads();

        cpB(it + 2); cp_commit();
        stsA(it + 1);
        ldgA(it + 2);

        const uint32_t a_st = (uint32_t)(it & 1) * 8192u;
        const uint32_t b_st = bsb + (uint32_t)(it % 3) * 8192u + b_off;
#pragma unroll
        for (int ks = 0; ks < 2; ks++) {
            uint32_t af[2][4];
            ldmatrix_x4(af[0], a_addr[0][ks] + a_st);
            ldmatrix_x4(af[1], a_addr[1][ks] + a_st);
            uint32_t bf[4][2];
#pragma unroll
            for (int ni = 0; ni < 4; ni++)
                asm volatile("ld.shared.v2.b32 {%0, %1}, [%2];"
                             : "=r"(bf[ni][0]), "=r"(bf[ni][1])
                             : "r"(b_st + (uint32_t)(ks * 4096 + ni * 256)));
#pragma unroll
            for (int mi = 0; mi < 2; mi++)
#pragma unroll
                for (int ni = 0; ni < 4; ni++)
                    mma_f16(acc[mi][ni], af[mi], bf[ni]);
        }
    }

    // epilogue -> split-K partials
    float* outp = g_part + (size_t)blockIdx.y * (NODES * NC);
#pragma unroll
    for (int mi = 0; mi < 2; mi++) {
        const int row = m0 + wm + mi * 16 + g;
#pragma unroll
        for (int ni = 0; ni < 4; ni++) {
            const int col = wn + ni * 8 + 2 * c;
            *(float2*)&outp[(size_t)row * NC + col] =
                make_float2(acc[mi][ni][0], acc[mi][ni][1]);
            *(float2*)&outp[(size_t)(row + 8) * NC + col] =
                make_float2(acc[mi][ni][2], acc[mi][ni][3]);
        }
    }
}

// ---------------------------------------------------------------------------
__global__ __launch_bounds__(256) void reduce_kernel(float* __restrict__ out) {
    const int i4 = (blockIdx.x * 256 + threadIdx.x) * 4;
    float4 s = make_float4(0.f, 0.f, 0.f, 0.f);
#pragma unroll
    for (int p = 0; p < SPLITS; p++) {
        const float4 v = *(const float4*)&g_part[(size_t)p * (NODES * NC) + i4];
        s.x += v.x; s.y += v.y; s.z += v.z; s.w += v.w;
    }
    *(float4*)&out[i4] = s;
}

// ---------------------------------------------------------------------------
extern "C" void kernel_launch(void* const* d_in, const int* in_sizes, int n_in,
                              void* d_out, int out_size) {
    const float* x   = (const float*)d_in[0];   // (4096, 32, 4)
    const float* adj = (const float*)d_in[1];   // (4096, 4096, 4)
    const float* w   = (const float*)d_in[2];   // (32, 32, 4)
    float* out = (float*)d_out;                 // (4096, 32, 4)
    (void)in_sizes; (void)n_in; (void)out_size;

    prep_kernel<<<512, 256>>>(x, w);
    gemm_kernel<<<dim3(NODES / BM, SPLITS), 512>>>(adj);
    reduce_kernel<<<(NODES * NC) / 1024, 256>>>(out);
}

// round 16
// speedup vs baseline: 1.1412x; 1.1412x over previous
#include <cuda_runtime.h>
#include <cuda_fp16.h>
#include <cstdint>

// ---------------------------------------------------------------------------
// out[n, e*4+a] = sum_{m,b} adj[n, m*4+b] * Vk[m*4+b, e*4+a]
// C[4096,128] = A[4096,16384] @ Vk.  A fp32 -> fp16 in-kernel, B packed fp16.
// mma.m16n8k16.f16.f32.  Split-K = 9.  BK=64 rhythm: conflict-free 128B-row
// A swizzle, half the barriers, A double- / B triple-buffered.
// ---------------------------------------------------------------------------
#define NODES 4096
#define KTOT  16384
#define NC    128

#define BM 128
#define BK 64
#define SPLITS 9
#define KB_TOTAL (KTOT / BK)    // 256 k-blocks (64 wide)
#define KB_PER   29             // splits 0..7: 29, split 8: 24

#define A_STAGE 16384           // 128 rows x 128 B
#define B_STAGE 16384           // 4 slabs x 4 KB
#define SMEM_TOTAL (2 * A_STAGE + 3 * B_STAGE)   // 81920

// B operand, fp16, fragment-packed per 16-k slab:
//   value B[k][col] at g_Vp[slab*2048 + col*16 + c*4 + j]
//   slab=k>>4, kk=k&15, c=(kk>>1)&3, j=(kk&1)|((kk>>3)<<1)
__device__ __align__(128) __half g_Vp[KTOT * NC];     // 4 MB
__device__ float g_part[SPLITS * NODES * NC];         // 18 MB

// ------------------------------ helpers ------------------------------------
__device__ __forceinline__ uint32_t smem_u32(const void* p) {
    uint32_t a;
    asm("{ .reg .u64 t; cvta.to.shared.u64 t, %1; cvt.u32.u64 %0, t; }"
        : "=r"(a) : "l"(p));
    return a;
}
__device__ __forceinline__ void cp_async16(uint32_t dst, const void* src) {
    asm volatile("cp.async.cg.shared.global [%0], [%1], 16;"
                 :: "r"(dst), "l"(src) : "memory");
}
__device__ __forceinline__ void cp_commit() {
    asm volatile("cp.async.commit_group;" ::: "memory");
}
template <int N>
__device__ __forceinline__ void cp_wait() {
    asm volatile("cp.async.wait_group %0;" :: "n"(N) : "memory");
}
__device__ __forceinline__ void ldmatrix_x4(uint32_t* r, uint32_t addr) {
    asm volatile("ldmatrix.sync.aligned.m8n8.x4.shared.b16 {%0,%1,%2,%3}, [%4];"
                 : "=r"(r[0]), "=r"(r[1]), "=r"(r[2]), "=r"(r[3]) : "r"(addr));
}
__device__ __forceinline__ void mma_f16(float* d, const uint32_t* a,
                                        const uint32_t* b) {
    asm volatile(
        "mma.sync.aligned.m16n8k16.row.col.f32.f16.f16.f32 "
        "{%0,%1,%2,%3}, {%4,%5,%6,%7}, {%8,%9}, {%0,%1,%2,%3};"
        : "+f"(d[0]), "+f"(d[1]), "+f"(d[2]), "+f"(d[3])
        : "r"(a[0]), "r"(a[1]), "r"(a[2]), "r"(a[3]), "r"(b[0]), "r"(b[1]));
}
__device__ __forceinline__ uint32_t cvt_f16x2(float lo, float hi) {
    uint32_t h;
    asm("cvt.rn.f16x2.f32 %0, %1, %2;" : "=r"(h) : "f"(hi), "f"(lo));
    return h;
}

// ---------------------------------------------------------------------------
// prep: 512 blocks x 256 thr; thread = (slab nh 0..1, column col 0..127).
// Rotation identity keeps ALL hot-loop indices compile-time.  (validated R13)
// ---------------------------------------------------------------------------
__global__ __launch_bounds__(256) void prep_kernel(const float* __restrict__ x,
                                                   const float* __restrict__ w) {
    __shared__ float ws[4096];                          // full W, 16 KB
    __shared__ float xs[1024];                          // 8 nodes x 128, 4 KB

    const int t = threadIdx.x;
#pragma unroll
    for (int i = 0; i < 4; i++)
        ((float4*)ws)[t + i * 256] = ((const float4*)w)[t + i * 256];
    ((float4*)xs)[t] =
        ((const float4*)(x + (size_t)blockIdx.x * 1024))[t];
    __syncthreads();

    const int nh = t >> 7;                              // slab in block
    const int col = t & 127;
    const int a = col & 3, e = col >> 2;

    int woff[4];
#pragma unroll
    for (int j = 0; j < 4; j++) woff[j] = e * 4 + ((a - j) & 3);

    float acc[4][4];                                    // [mi][j] rotated
#pragma unroll
    for (int mi = 0; mi < 4; mi++)
#pragma unroll
        for (int j = 0; j < 4; j++) acc[mi][j] = 0.f;

#pragma unroll
    for (int d = 0; d < 32; d++) {
        float wr[4];
#pragma unroll
        for (int j = 0; j < 4; j++) wr[j] = ws[d * 128 + woff[j]];
#pragma unroll
        for (int mi = 0; mi < 4; mi++) {
            const float4 xv = *(const float4*)&xs[(nh * 4 + mi) * 128 + d * 4];
            acc[mi][0] += xv.x * wr[0];
            acc[mi][1] += xv.y * wr[1];
            acc[mi][2] += xv.z * wr[2];
            acc[mi][3] += xv.w * wr[3];
        }
    }

    __align__(16) __half hbuf[16];
#pragma unroll
    for (int mi = 0; mi < 4; mi++)
#pragma unroll
        for (int j = 0; j < 4; j++) {
            const int b = (a - j) & 3;
            const int kk = mi * 4 + b;
            const int pos = ((kk >> 1) & 3) * 4 + (kk & 1) + ((kk >> 3) << 1);
            hbuf[pos] = __float2half_rn(acc[mi][j]);
        }
    const size_t slab = (size_t)blockIdx.x * 2 + nh;
    uint4* dst = (uint4*)(g_Vp + slab * 2048 + col * 16);
    dst[0] = ((const uint4*)hbuf)[0];
    dst[1] = ((const uint4*)hbuf)[1];
}

// ---------------------------------------------------------------------------
// GEMM: grid (32 m-tiles, 9 splits), 256 thr = 8 warps (4m x 2n),
// warp tile 32x64, mma m16n8k16 f16.f32.  BK=64: A rows 128 B, swizzle
// ch = (ks*2+khalf) ^ (r&7) -> ldmatrix conflict-free.
// ---------------------------------------------------------------------------
__global__ __launch_bounds__(256, 2) void gemm_kernel(const float* __restrict__ A) {
    extern __shared__ __align__(16) char smem[];
    const uint32_t asb = smem_u32(smem);                // A: 2 x 16 KB
    const uint32_t bsb = asb + 2 * A_STAGE;             // B: 3 x 16 KB

    const int tid = threadIdx.x;
    const int lane = tid & 31;
    const int wid = tid >> 5;
    const int wm = (wid & 3) * 32;
    const int wn = (wid >> 2) * 64;
    const int g = lane >> 2;
    const int c = lane & 3;

    const int m0 = blockIdx.x * BM;
    const int kb0 = blockIdx.y * KB_PER;
    const int cnt = min(KB_PER, KB_TOTAL - kb0);
    const int k0 = kb0 * BK;
    const __half* Bsrc = g_Vp + (size_t)(k0 >> 4) * 2048;

    // A ldmatrix: row_l = lane&15 pattern, khalf = lane>>4, rx = r&7 = lane&7
    const int row_l = (lane & 7) | (((lane >> 3) & 1) << 3);
    const int khalf = lane >> 4;
    const int rx = lane & 7;
    uint32_t ab[2];
#pragma unroll
    for (int mi = 0; mi < 2; mi++)
        ab[mi] = asb + (uint32_t)((wm + mi * 16 + row_l) * 128);
    const uint32_t b_off = (uint32_t)((wn + g) * 32 + c * 8);

    const int a_row = tid >> 3;                         // 0..31
    const int a_kq = tid & 7;

    float acc[2][8][4];
#pragma unroll
    for (int mi = 0; mi < 2; mi++)
#pragma unroll
        for (int ni = 0; ni < 8; ni++)
#pragma unroll
            for (int j = 0; j < 4; j++) acc[mi][ni][j] = 0.f;

    float4 pf[4];
    auto ldgA = [&](int it, int h) {
        if (it < cnt) {
            const int ko = k0 + it * BK + h * 32;
#pragma unroll
            for (int p = 0; p < 4; p++)
                pf[p] = *(const float4*)(A + (size_t)(m0 + a_row + p * 32) * KTOT +
                                         ko + a_kq * 4);
        }
    };
    auto stsA = [&](int it, int h) {
        if (it < cnt) {
            const uint32_t base = asb + (uint32_t)(it & 1) * A_STAGE;
#pragma unroll
            for (int p = 0; p < 4; p++) {
                const int row = a_row + p * 32;
                const int ch = (h * 4 + (a_kq >> 1)) ^ (row & 7);
                const uint32_t off =
                    (uint32_t)(row * 128 + ch * 16 + (a_kq & 1) * 8);
                const uint32_t h0 = cvt_f16x2(pf[p].x, pf[p].y);
                const uint32_t h1 = cvt_f16x2(pf[p].z, pf[p].w);
                asm volatile("st.shared.v2.b32 [%0], {%1, %2};"
                             :: "r"(base + off), "r"(h0), "r"(h1) : "memory");
            }
        }
    };
    auto cpB = [&](int it) {
        if (it < cnt) {
            const uint32_t bd = bsb + (uint32_t)(it % 3) * B_STAGE;
            const char* src = (const char*)(Bsrc + (size_t)it * 8192);
#pragma unroll
            for (int p = 0; p < 4; p++) {
                const int idx = tid + p * 256;
                cp_async16(bd + (uint32_t)idx * 16, src + idx * 16);
            }
        }
    };

    // prologue: fill A stage 0; start B stages 0,1
    ldgA(0, 0); stsA(0, 0);
    ldgA(0, 1); stsA(0, 1);
    cpB(0); cp_commit();
    cpB(1); cp_commit();
    ldgA(1, 0);

    for (int it = 0; it < cnt; it++) {
        cp_wait<1>();
        __syncthreads();

        cpB(it + 2); cp_commit();

        const uint32_t a_st = (uint32_t)(it & 1) * A_STAGE;
        const uint32_t b_st = bsb + (uint32_t)(it % 3) * B_STAGE + b_off;

        // compute ks 0..1 while A(it+1, h0) LDG is in flight
#pragma unroll
        for (int ks = 0; ks < 2; ks++) {
            uint32_t af[2][4];
#pragma unroll
            for (int mi = 0; mi < 2; mi++) {
                const uint32_t ko =
                    (uint32_t)((((ks * 2 + khalf) ^ rx)) * 16);
                ldmatrix_x4(af[mi], ab[mi] + a_st + ko);
            }
            uint32_t bf[8][2];
#pragma unroll
            for (int ni = 0; ni < 8; ni++)
                asm volatile("ld.shared.v2.b32 {%0, %1}, [%2];"
                             : "=r"(bf[ni][0]), "=r"(bf[ni][1])
                             : "r"(b_st + (uint32_t)(ks * 4096 + ni * 256)));
#pragma unroll
            for (int mi = 0; mi < 2; mi++)
#pragma unroll
                for (int ni = 0; ni < 8; ni++)
                    mma_f16(acc[mi][ni], af[mi], bf[ni]);
        }

        stsA(it + 1, 0);
        ldgA(it + 1, 1);

#pragma unroll
        for (int ks = 2; ks < 4; ks++) {
            uint32_t af[2][4];
#pragma unroll
            for (int mi = 0; mi < 2; mi++) {
                const uint32_t ko =
                    (uint32_t)((((ks * 2 + khalf) ^ rx)) * 16);
                ldmatrix_x4(af[mi], ab[mi] + a_st + ko);
            }
            uint32_t bf[8][2];
#pragma unroll
            for (int ni = 0; ni < 8; ni++)
                asm volatile("ld.shared.v2.b32 {%0, %1}, [%2];"
                             : "=r"(bf[ni][0]), "=r"(bf[ni][1])
                             : "r"(b_st + (uint32_t)(ks * 4096 + ni * 256)));
#pragma unroll
            for (int mi = 0; mi < 2; mi++)
#pragma unroll
                for (int ni = 0; ni < 8; ni++)
                    mma_f16(acc[mi][ni], af[mi], bf[ni]);
        }

        stsA(it + 1, 1);
        ldgA(it + 2, 0);
    }

    // epilogue -> split-K partials
    float* outp = g_part + (size_t)blockIdx.y * (NODES * NC);
#pragma unroll
    for (int mi = 0; mi < 2; mi++) {
        const int row = m0 + wm + mi * 16 + g;
#pragma unroll
        for (int ni = 0; ni < 8; ni++) {
            const int col = wn + ni * 8 + 2 * c;
            *(float2*)&outp[(size_t)row * NC + col] =
                make_float2(acc[mi][ni][0], acc[mi][ni][1]);
            *(float2*)&outp[(size_t)(row + 8) * NC + col] =
                make_float2(acc[mi][ni][2], acc[mi][ni][3]);
        }
    }
}

// ---------------------------------------------------------------------------
__global__ __launch_bounds__(256) void reduce_kernel(float* __restrict__ out) {
    const int i4 = (blockIdx.x * 256 + threadIdx.x) * 4;
    float4 s = make_float4(0.f, 0.f, 0.f, 0.f);
#pragma unroll
    for (int p = 0; p < SPLITS; p++) {
        const float4 v = *(const float4*)&g_part[(size_t)p * (NODES * NC) + i4];
        s.x += v.x; s.y += v.y; s.z += v.z; s.w += v.w;
    }
    *(float4*)&out[i4] = s;
}

// ---------------------------------------------------------------------------
extern "C" void kernel_launch(void* const* d_in, const int* in_sizes, int n_in,
                              void* d_out, int out_size) {
    const float* x   = (const float*)d_in[0];   // (4096, 32, 4)
    const float* adj = (const float*)d_in[1];   // (4096, 4096, 4)
    const float* w   = (const float*)d_in[2];   // (32, 32, 4)
    float* out = (float*)d_out;                 // (4096, 32, 4)
    (void)in_sizes; (void)n_in; (void)out_size;

    cudaFuncSetAttribute(gemm_kernel,
                         cudaFuncAttributeMaxDynamicSharedMemorySize, SMEM_TOTAL);

    prep_kernel<<<512, 256>>>(x, w);
    gemm_kernel<<<dim3(NODES / BM, SPLITS), 256, SMEM_TOTAL>>>(adj);
    reduce_kernel<<<(NODES * NC) / 1024, 256>>>(out);
}

// round 17
// speedup vs baseline: 1.1712x; 1.0263x over previous
#include <cuda_runtime.h>
#include <cuda_fp16.h>
#include <cstdint>

// ---------------------------------------------------------------------------
// out[n, e*4+a] = sum_{m,b} adj[n, m*4+b] * Vk[m*4+b, e*4+a]
// C[4096,128] = A[4096,16384] @ Vk.  A streamed as RAW FP32 via cp.async
// (deep async queue -> high MLP); fragments built from fp32 smem with
// conflict-free LDS.64 + cvt.f16x2.  B packed fp16 (prep).  Split-K = 9.
// ---------------------------------------------------------------------------
#define NODES 4096
#define KTOT  16384
#define NC    128

#define BM 128
#define BK 32
#define SPLITS 9
#define KB_TOTAL (KTOT / BK)    // 512 k-blocks
#define KB_PER   57             // splits 0..7: 57, split 8: 56

#define AS_STRIDE 40                        // floats per A smem row (conflict-free)
#define A_STAGE_B (128 * AS_STRIDE * 4)     // 20480 B
#define B_STAGE_B 8192
#define STAGES 3
#define SMEM_TOTAL (STAGES * (A_STAGE_B + B_STAGE_B))   // 86016 B

// B operand, fp16, fragment-packed per 16-k slab:
//   value B[k][col] at g_Vp[slab*2048 + col*16 + c*4 + j]
//   slab=k>>4, kk=k&15, c=(kk>>1)&3, j=(kk&1)|((kk>>3)<<1)
__device__ __align__(128) __half g_Vp[KTOT * NC];     // 4 MB
__device__ float g_part[SPLITS * NODES * NC];         // 18 MB

// ------------------------------ helpers ------------------------------------
__device__ __forceinline__ uint32_t smem_u32(const void* p) {
    uint32_t a;
    asm("{ .reg .u64 t; cvta.to.shared.u64 t, %1; cvt.u32.u64 %0, t; }"
        : "=r"(a) : "l"(p));
    return a;
}
__device__ __forceinline__ void cp_async16(uint32_t dst, const void* src) {
    asm volatile("cp.async.cg.shared.global [%0], [%1], 16;"
                 :: "r"(dst), "l"(src) : "memory");
}
__device__ __forceinline__ void cp_commit() {
    asm volatile("cp.async.commit_group;" ::: "memory");
}
template <int N>
__device__ __forceinline__ void cp_wait() {
    asm volatile("cp.async.wait_group %0;" :: "n"(N) : "memory");
}
__device__ __forceinline__ void mma_f16(float* d, const uint32_t* a,
                                        const uint32_t* b) {
    asm volatile(
        "mma.sync.aligned.m16n8k16.row.col.f32.f16.f16.f32 "
        "{%0,%1,%2,%3}, {%4,%5,%6,%7}, {%8,%9}, {%0,%1,%2,%3};"
        : "+f"(d[0]), "+f"(d[1]), "+f"(d[2]), "+f"(d[3])
        : "r"(a[0]), "r"(a[1]), "r"(a[2]), "r"(a[3]), "r"(b[0]), "r"(b[1]));
}
__device__ __forceinline__ uint32_t cvt_f16x2(float lo, float hi) {
    uint32_t h;
    asm("cvt.rn.f16x2.f32 %0, %1, %2;" : "=r"(h) : "f"(hi), "f"(lo));
    return h;
}
__device__ __forceinline__ float2 lds_f2(uint32_t addr) {
    float2 v;
    asm volatile("ld.shared.v2.f32 {%0, %1}, [%2];"
                 : "=f"(v.x), "=f"(v.y) : "r"(addr));
    return v;
}

// ---------------------------------------------------------------------------
// prep: 512 blocks x 256 thr; thread = (slab nh 0..1, column col 0..127).
// Rotation identity keeps ALL hot-loop indices compile-time.  (validated R13)
// ---------------------------------------------------------------------------
__global__ __launch_bounds__(256) void prep_kernel(const float* __restrict__ x,
                                                   const float* __restrict__ w) {
    __shared__ float ws[4096];                          // full W, 16 KB
    __shared__ float xs[1024];                          // 8 nodes x 128, 4 KB

    const int t = threadIdx.x;
#pragma unroll
    for (int i = 0; i < 4; i++)
        ((float4*)ws)[t + i * 256] = ((const float4*)w)[t + i * 256];
    ((float4*)xs)[t] =
        ((const float4*)(x + (size_t)blockIdx.x * 1024))[t];
    __syncthreads();

    const int nh = t >> 7;                              // slab in block
    const int col = t & 127;
    const int a = col & 3, e = col >> 2;

    int woff[4];
#pragma unroll
    for (int j = 0; j < 4; j++) woff[j] = e * 4 + ((a - j) & 3);

    float acc[4][4];                                    // [mi][j] rotated
#pragma unroll
    for (int mi = 0; mi < 4; mi++)
#pragma unroll
        for (int j = 0; j < 4; j++) acc[mi][j] = 0.f;

#pragma unroll
    for (int d = 0; d < 32; d++) {
        float wr[4];
#pragma unroll
        for (int j = 0; j < 4; j++) wr[j] = ws[d * 128 + woff[j]];
#pragma unroll
        for (int mi = 0; mi < 4; mi++) {
            const float4 xv = *(const float4*)&xs[(nh * 4 + mi) * 128 + d * 4];
            acc[mi][0] += xv.x * wr[0];
            acc[mi][1] += xv.y * wr[1];
            acc[mi][2] += xv.z * wr[2];
            acc[mi][3] += xv.w * wr[3];
        }
    }

    __align__(16) __half hbuf[16];
#pragma unroll
    for (int mi = 0; mi < 4; mi++)
#pragma unroll
        for (int j = 0; j < 4; j++) {
            const int b = (a - j) & 3;
            const int kk = mi * 4 + b;
            const int pos = ((kk >> 1) & 3) * 4 + (kk & 1) + ((kk >> 3) << 1);
            hbuf[pos] = __float2half_rn(acc[mi][j]);
        }
    const size_t slab = (size_t)blockIdx.x * 2 + nh;
    uint4* dst = (uint4*)(g_Vp + slab * 2048 + col * 16);
    dst[0] = ((const uint4*)hbuf)[0];
    dst[1] = ((const uint4*)hbuf)[1];
}

// ---------------------------------------------------------------------------
// GEMM: grid (32 m-tiles, 9 splits), 256 thr = 8 warps (4m x 2n),
// warp tile 32x64, mma m16n8k16 f16.f32.  A via cp.async (fp32) +
// LDS.64/cvt fragment build; B via cp.async (packed fp16).  3 stages.
// ---------------------------------------------------------------------------
__global__ __launch_bounds__(256, 2) void gemm_kernel(const float* __restrict__ A) {
    extern __shared__ __align__(16) char smem[];
    const uint32_t asb = smem_u32(smem);                 // A: 3 x 20480 B
    const uint32_t bsb = asb + STAGES * A_STAGE_B;       // B: 3 x 8192 B

    const int tid = threadIdx.x;
    const int lane = tid & 31;
    const int wid = tid >> 5;
    const int wm = (wid & 3) * 32;
    const int wn = (wid >> 2) * 64;
    const int g = lane >> 2;
    const int c = lane & 3;

    const int m0 = blockIdx.x * BM;
    const int kb0 = blockIdx.y * KB_PER;
    const int cnt = min(KB_PER, KB_TOTAL - kb0);
    const int k0 = kb0 * BK;
    const __half* Bsrc = g_Vp + (size_t)(k0 >> 4) * 2048;

    // A fragment base addresses (fp32 smem, stride 40 floats = 160 B):
    // rows wm+mi*16+g (+8), k = ks*16 + 2c (+8)
    uint32_t afrag[2];                                   // per mi, ks/k offsets added
#pragma unroll
    for (int mi = 0; mi < 2; mi++)
        afrag[mi] = asb + (uint32_t)((wm + mi * 16 + g) * 160 + c * 8);
    const uint32_t b_off = (uint32_t)((wn + g) * 32 + c * 8);

    const int a_r = tid >> 3;                            // loader row 0..31
    const int a_q = tid & 7;                             // 16B chunk in row

    float acc[2][8][4];
#pragma unroll
    for (int mi = 0; mi < 2; mi++)
#pragma unroll
        for (int ni = 0; ni < 8; ni++)
#pragma unroll
            for (int j = 0; j < 4; j++) acc[mi][ni][j] = 0.f;

    auto cpStage = [&](int it) {
        if (it < cnt) {
            const int ko = k0 + it * BK;
            const uint32_t ad = asb + (uint32_t)(it % STAGES) * A_STAGE_B;
#pragma unroll
            for (int p = 0; p < 4; p++) {
                const int row = a_r + p * 32;
                cp_async16(ad + (uint32_t)(row * 160 + a_q * 16),
                           A + (size_t)(m0 + row) * KTOT + ko + a_q * 4);
            }
            const uint32_t bd = bsb + (uint32_t)(it % STAGES) * B_STAGE_B;
            const char* src = (const char*)(Bsrc + (size_t)it * 4096);
#pragma unroll
            for (int p = 0; p < 2; p++) {
                const int idx = tid + p * 256;
                cp_async16(bd + (uint32_t)idx * 16, src + idx * 16);
            }
        }
    };

    // prologue: stages 0,1 in flight
    cpStage(0); cp_commit();
    cpStage(1); cp_commit();

    for (int it = 0; it < cnt; it++) {
        cp_wait<1>();
        __syncthreads();

        // stage (it+2)%3 == (it-1)%3: safe, compute(it-1) closed by the sync
        cpStage(it + 2); cp_commit();

        const uint32_t a_st = (uint32_t)(it % STAGES) * A_STAGE_B;
        const uint32_t b_st = bsb + (uint32_t)(it % STAGES) * B_STAGE_B + b_off;
#pragma unroll
        for (int ks = 0; ks < 2; ks++) {
            uint32_t af[2][4];
#pragma unroll
            for (int mi = 0; mi < 2; mi++) {
                const uint32_t base = afrag[mi] + a_st + (uint32_t)(ks * 64);
                const float2 v0 = lds_f2(base);                 // (g,   k)
                const float2 v1 = lds_f2(base + 8 * 160);       // (g+8, k)
                const float2 v2 = lds_f2(base + 32);            // (g,   k+8)
                const float2 v3 = lds_f2(base + 8 * 160 + 32);  // (g+8, k+8)
                af[mi][0] = cvt_f16x2(v0.x, v0.y);
                af[mi][1] = cvt_f16x2(v1.x, v1.y);
                af[mi][2] = cvt_f16x2(v2.x, v2.y);
                af[mi][3] = cvt_f16x2(v3.x, v3.y);
            }
            uint32_t bf[8][2];
#pragma unroll
            for (int ni = 0; ni < 8; ni++)
                asm volatile("ld.shared.v2.b32 {%0, %1}, [%2];"
                             : "=r"(bf[ni][0]), "=r"(bf[ni][1])
                             : "r"(b_st + (uint32_t)(ks * 4096 + ni * 256)));
#pragma unroll
            for (int mi = 0; mi < 2; mi++)
#pragma unroll
                for (int ni = 0; ni < 8; ni++)
                    mma_f16(acc[mi][ni], af[mi], bf[ni]);
        }
    }

    // epilogue -> split-K partials
    float* outp = g_part + (size_t)blockIdx.y * (NODES * NC);
#pragma unroll
    for (int mi = 0; mi < 2; mi++) {
        const int row = m0 + wm + mi * 16 + g;
#pragma unroll
        for (int ni = 0; ni < 8; ni++) {
            const int col = wn + ni * 8 + 2 * c;
            *(float2*)&outp[(size_t)row * NC + col] =
                make_float2(acc[mi][ni][0], acc[mi][ni][1]);
            *(float2*)&outp[(size_t)(row + 8) * NC + col] =
                make_float2(acc[mi][ni][2], acc[mi][ni][3]);
        }
    }
}

// ---------------------------------------------------------------------------
__global__ __launch_bounds__(256) void reduce_kernel(float* __restrict__ out) {
    const int i4 = (blockIdx.x * 256 + threadIdx.x) * 4;
    float4 s = make_float4(0.f, 0.f, 0.f, 0.f);
#pragma unroll
    for (int p = 0; p < SPLITS; p++) {
        const float4 v = *(const float4*)&g_part[(size_t)p * (NODES * NC) + i4];
        s.x += v.x; s.y += v.y; s.z += v.z; s.w += v.w;
    }
    *(float4*)&out[i4] = s;
}

// ---------------------------------------------------------------------------
extern "C" void kernel_launch(void* const* d_in, const int* in_sizes, int n_in,
                              void* d_out, int out_size) {
    const float* x   = (const float*)d_in[0];   // (4096, 32, 4)
    const float* adj = (const float*)d_in[1];   // (4096, 4096, 4)
    const float* w   = (const float*)d_in[2];   // (32, 32, 4)
    float* out = (float*)d_out;                 // (4096, 32, 4)
    (void)in_sizes; (void)n_in; (void)out_size;

    cudaFuncSetAttribute(gemm_kernel,
                         cudaFuncAttributeMaxDynamicSharedMemorySize, SMEM_TOTAL);

    prep_kernel<<<512, 256>>>(x, w);
    gemm_kernel<<<dim3(NODES / BM, SPLITS), 256, SMEM_TOTAL>>>(adj);
    reduce_kernel<<<(NODES * NC) / 1024, 256>>>(out);
}